// round 1
// baseline (speedup 1.0000x reference)
#include <cuda_runtime.h>
#include <math.h>

// Phase 1: energies[b*2048 + s] = dot(hidden[b,:], enc[s,b,:])
// One warp per (s,b) row. Row = s*64 + b laid out contiguously (1024 floats).
__global__ void __launch_bounds__(256) dot_kernel(
    const float* __restrict__ hidden,   // [64, 1024]
    const float* __restrict__ enc,      // [2048, 64, 1024]
    float* __restrict__ energies)       // [64, 2048]
{
    int gwarp = (blockIdx.x * blockDim.x + threadIdx.x) >> 5;   // 0..131071
    int lane  = threadIdx.x & 31;

    int b = gwarp & 63;
    int s = gwarp >> 6;

    const float4* row = reinterpret_cast<const float4*>(enc + (size_t)gwarp * 1024);
    const float4* h   = reinterpret_cast<const float4*>(hidden + (size_t)b * 1024);

    float acc = 0.0f;
#pragma unroll
    for (int i = 0; i < 8; i++) {
        float4 e  = row[lane + i * 32];
        float4 hv = __ldg(&h[lane + i * 32]);
        acc = fmaf(e.x, hv.x, acc);
        acc = fmaf(e.y, hv.y, acc);
        acc = fmaf(e.z, hv.z, acc);
        acc = fmaf(e.w, hv.w, acc);
    }
#pragma unroll
    for (int o = 16; o; o >>= 1)
        acc += __shfl_xor_sync(0xffffffffu, acc, o);

    if (lane == 0)
        energies[b * 2048 + s] = acc;
}

// Phase 2: in-place softmax over S=2048 per batch row. 64 blocks x 256 threads.
__global__ void __launch_bounds__(256) softmax_kernel(float* __restrict__ out)
{
    __shared__ float red_max[8];
    __shared__ float red_sum[8];

    int b   = blockIdx.x;
    int tid = threadIdx.x;
    float* p = out + (size_t)b * 2048;

    float v[8];
    float m = -INFINITY;
#pragma unroll
    for (int i = 0; i < 8; i++) {
        v[i] = p[tid + i * 256];
        m = fmaxf(m, v[i]);
    }
#pragma unroll
    for (int o = 16; o; o >>= 1)
        m = fmaxf(m, __shfl_xor_sync(0xffffffffu, m, o));
    if ((tid & 31) == 0) red_max[tid >> 5] = m;
    __syncthreads();
    if (tid < 32) {
        float x = (tid < 8) ? red_max[tid] : -INFINITY;
#pragma unroll
        for (int o = 4; o; o >>= 1)
            x = fmaxf(x, __shfl_xor_sync(0xffffffffu, x, o));
        if (tid == 0) red_max[0] = x;
    }
    __syncthreads();
    m = red_max[0];

    float s = 0.0f;
#pragma unroll
    for (int i = 0; i < 8; i++) {
        v[i] = expf(v[i] - m);
        s += v[i];
    }
#pragma unroll
    for (int o = 16; o; o >>= 1)
        s += __shfl_xor_sync(0xffffffffu, s, o);
    if ((tid & 31) == 0) red_sum[tid >> 5] = s;
    __syncthreads();
    if (tid < 32) {
        float x = (tid < 8) ? red_sum[tid] : 0.0f;
#pragma unroll
        for (int o = 4; o; o >>= 1)
            x += __shfl_xor_sync(0xffffffffu, x, o);
        if (tid == 0) red_sum[0] = x;
    }
    __syncthreads();
    float inv = 1.0f / red_sum[0];

#pragma unroll
    for (int i = 0; i < 8; i++)
        p[tid + i * 256] = v[i] * inv;
}

extern "C" void kernel_launch(void* const* d_in, const int* in_sizes, int n_in,
                              void* d_out, int out_size)
{
    const float* hidden = (const float*)d_in[0];   // [1, 64, 1024]
    const float* enc    = (const float*)d_in[1];   // [2048, 64, 1024]
    float* out          = (float*)d_out;           // [64, 1, 2048]

    // 131072 rows, 1 warp each, 8 warps (256 thr) per block -> 16384 blocks
    dot_kernel<<<16384, 256>>>(hidden, enc, out);
    softmax_kernel<<<64, 256>>>(out);
}